// round 6
// baseline (speedup 1.0000x reference)
#include <cuda_runtime.h>

#define NMAX 100000
#define EMAX 3200000
#define HDIM 64

// Scratch (no allocations allowed)
__device__ __align__(128) int   g_cnt[NMAX];        // in-degree (without self loop)
__device__ __align__(128) int   g_off[NMAX];        // exclusive segment start
__device__ __align__(128) int   g_cur[NMAX];        // atomic cursor for sort scatter
__device__ __align__(128) int   g_bsum[512];        // block sums for scan
__device__ __align__(128) float g_dis[NMAX];        // rsqrt(deg)
__device__ __align__(128) int   g_srow[EMAX];       // source indices sorted by target
__device__ __align__(128) float g_xs1[NMAX * HDIM]; // layer1 xw * dis[n]
__device__ __align__(128) float g_h1 [NMAX * HDIM];
__device__ __align__(128) float g_xs2[NMAX * HDIM];
__device__ __align__(128) float g_h2 [NMAX * HDIM];

// ---------------------------------------------------------------------------
// Phase 0: counting sort of edges by target column.
// NOTE: edge_index arrives as int32 (JAX x64 disabled -> int64 decays to int32).
// ---------------------------------------------------------------------------
__global__ void k_zero(int n) {
    int i = blockIdx.x * blockDim.x + threadIdx.x;
    if (i < n) g_cnt[i] = 0;
}

__global__ void k_count(const int* __restrict__ ei, int E) {
    int e = blockIdx.x * blockDim.x + threadIdx.x;
    if (e < E) {
        int c = __ldg(&ei[E + e]);
        atomicAdd(&g_cnt[c], 1);
    }
}

// per-block exclusive scan of g_cnt -> g_off; block totals -> g_bsum
__global__ void k_scan1(int n) {
    __shared__ int s[256];
    int t = threadIdx.x;
    int i = blockIdx.x * 256 + t;
    int v = (i < n) ? g_cnt[i] : 0;
    s[t] = v;
    __syncthreads();
#pragma unroll
    for (int o = 1; o < 256; o <<= 1) {
        int u = (t >= o) ? s[t - o] : 0;
        __syncthreads();
        s[t] += u;
        __syncthreads();
    }
    if (i < n) g_off[i] = s[t] - v;          // exclusive within block
    if (t == 255) g_bsum[blockIdx.x] = s[255];
}

// single-block exclusive scan of block sums (nb <= 512)
__global__ void k_scan2(int nb) {
    __shared__ int s[512];
    int t = threadIdx.x;
    int v = (t < nb) ? g_bsum[t] : 0;
    s[t] = v;
    __syncthreads();
#pragma unroll
    for (int o = 1; o < 512; o <<= 1) {
        int u = (t >= o) ? s[t - o] : 0;
        __syncthreads();
        s[t] += u;
        __syncthreads();
    }
    if (t < nb) g_bsum[t] = s[t] - v;        // exclusive
}

// add block prefix; init cursor; compute dis = rsqrt(deg) (deg = cnt + self)
__global__ void k_scan3(int n) {
    int i = blockIdx.x * 256 + threadIdx.x;
    if (i < n) {
        int o = g_off[i] + g_bsum[blockIdx.x];
        g_off[i] = o;
        g_cur[i] = o;
        g_dis[i] = rsqrtf((float)(g_cnt[i] + 1));
    }
}

__global__ void k_sort(const int* __restrict__ ei, int E) {
    int e = blockIdx.x * blockDim.x + threadIdx.x;
    if (e < E) {
        int r = __ldg(&ei[e]);
        int c = __ldg(&ei[E + e]);
        int pos = atomicAdd(&g_cur[c], 1);
        g_srow[pos] = r;
    }
}

// ---------------------------------------------------------------------------
// Layer 1 GEMM: xs1 = (x @ W1) * dis   (16 -> 64). 4 nodes / 256-thread block.
// ---------------------------------------------------------------------------
__global__ void k_gemm1(const float* __restrict__ x,
                        const float* __restrict__ W1, int n) {
    __shared__ float sW[16 * 64];
    __shared__ float sx[4][16];
    int t = threadIdx.x;
    for (int i = t; i < 16 * 64; i += 256) sW[i] = W1[i];
    int node0 = blockIdx.x * 4;
    if (t < 64) {
        int nn = t >> 4, k = t & 15;
        int node = node0 + nn;
        sx[nn][k] = (node < n) ? x[node * 16 + k] : 0.0f;
    }
    __syncthreads();
    int nn = t >> 6, f = t & 63;
    int node = node0 + nn;
    if (node < n) {
        float acc = 0.0f;
#pragma unroll
        for (int k = 0; k < 16; k++) acc += sx[nn][k] * sW[k * 64 + f];
        g_xs1[(size_t)node * HDIM + f] = acc * g_dis[node];
    }
}

// ---------------------------------------------------------------------------
// Gather: h[c] = dis[c] * (xs[c] + sum_{edges into c} xs[row]) + b
// 16 threads per node, float4 lanes, register accumulation, no atomics.
// Index prefetch pipelines the srow load past the dependent xs load.
// ---------------------------------------------------------------------------
__global__ void __launch_bounds__(256) k_gather(int n, int layer,
                                                const float* __restrict__ bvec) {
    int gtid = blockIdx.x * blockDim.x + threadIdx.x;
    int node = gtid >> 4;
    int q = gtid & 15;
    if (node >= n) return;
    const float4* xs = (const float4*)(layer ? g_xs2 : g_xs1);
    float4*       h  = (float4*)(layer ? g_h2  : g_h1);

    // hoist all non-loop-dependent loads up front
    float4 b = __ldg(((const float4*)bvec) + q);
    float  d = g_dis[node];
    int    s = g_off[node];
    int    cnt = g_cnt[node];

    float4 a = xs[(size_t)node * 16 + q];      // self-loop term
    float ax = a.x, ay = a.y, az = a.z, aw = a.w;

    int e = s + cnt;
    if (cnt > 0) {
        int r_next = __ldg(&g_srow[s]);
#pragma unroll 2
        for (int i = s; i < e; i++) {
            int r = r_next;
            if (i + 1 < e) r_next = __ldg(&g_srow[i + 1]);
            float4 v = __ldg(&xs[(size_t)r * 16 + q]);
            ax += v.x; ay += v.y; az += v.z; aw += v.w;
        }
    }
    float4 o;
    o.x = ax * d + b.x;
    o.y = ay * d + b.y;
    o.z = az * d + b.z;
    o.w = aw * d + b.w;
    h[(size_t)node * 16 + q] = o;
}

// ---------------------------------------------------------------------------
// Layer 2 GEMM: xs2 = (relu(h1) @ W2) * dis  (64 -> 64).
// ---------------------------------------------------------------------------
__global__ void k_gemm2(const float* __restrict__ W2, int n) {
    __shared__ float sW[64 * 64];
    __shared__ float sh[4][64];
    int t = threadIdx.x;
    for (int i = t; i < 64 * 64; i += 256) sW[i] = W2[i];
    int node0 = blockIdx.x * 4;
    {
        int nn = t >> 6, k = t & 63;
        int node = node0 + nn;
        sh[nn][k] = (node < n) ? fmaxf(g_h1[(size_t)node * HDIM + k], 0.0f) : 0.0f;
    }
    __syncthreads();
    int nn = t >> 6, f = t & 63;
    int node = node0 + nn;
    if (node < n) {
        float acc = 0.0f;
#pragma unroll
        for (int k = 0; k < 64; k++) acc += sh[nn][k] * sW[k * 64 + f];
        g_xs2[(size_t)node * HDIM + f] = acc * g_dis[node];
    }
}

// ---------------------------------------------------------------------------
// Final head: out[n] = sigmoid( relu(h2[n]) . Wf + bf ). One warp per node.
// ---------------------------------------------------------------------------
__global__ void k_final(const float* __restrict__ Wf,
                        const float* __restrict__ bf,
                        float* __restrict__ out, int n) {
    int gtid = blockIdx.x * blockDim.x + threadIdx.x;
    int node = gtid >> 5;
    int lane = threadIdx.x & 31;
    if (node >= n) return;
    const float* h = g_h2 + (size_t)node * HDIM;
    float s = fmaxf(h[lane], 0.0f) * __ldg(&Wf[lane])
            + fmaxf(h[lane + 32], 0.0f) * __ldg(&Wf[lane + 32]);
#pragma unroll
    for (int o = 16; o > 0; o >>= 1) s += __shfl_down_sync(0xffffffffu, s, o);
    if (lane == 0) {
        float z = s + bf[0];
        out[node] = 1.0f / (1.0f + expf(-z));
    }
}

// ---------------------------------------------------------------------------
extern "C" void kernel_launch(void* const* d_in, const int* in_sizes, int n_in,
                              void* d_out, int out_size) {
    const float* x  = (const float*)d_in[0];
    const int*   ei = (const int*)d_in[1];    // int32: JAX x64 disabled
    const float* W1 = (const float*)d_in[2];
    const float* b1 = (const float*)d_in[3];
    const float* W2 = (const float*)d_in[4];
    const float* b2 = (const float*)d_in[5];
    const float* Wf = (const float*)d_in[6];
    const float* bf = (const float*)d_in[7];
    float* out = (float*)d_out;

    int N = in_sizes[0] / 16;   // 100000
    int E = in_sizes[1] / 2;    // 3200000

    int nb = (N + 255) / 256;   // 391 blocks (<= 512 for scan2)
    int eb = (E + 255) / 256;
    int gb = (N + 3) / 4;
    int gth = (N * 16 + 255) / 256;
    int fb = (N * 32 + 255) / 256;

    // sort phase
    k_zero  <<<nb, 256>>>(N);
    k_count <<<eb, 256>>>(ei, E);
    k_scan1 <<<nb, 256>>>(N);
    k_scan2 <<<1, 512>>>(nb);
    k_scan3 <<<nb, 256>>>(N);
    k_sort  <<<eb, 256>>>(ei, E);

    // layer 1
    k_gemm1  <<<gb, 256>>>(x, W1, N);
    k_gather <<<gth, 256>>>(N, 0, b1);

    // layer 2
    k_gemm2  <<<gb, 256>>>(W2, N);
    k_gather <<<gth, 256>>>(N, 1, b2);

    // head
    k_final <<<fb, 256>>>(Wf, bf, out, N);
}

// round 16
// speedup vs baseline: 1.1670x; 1.1670x over previous
#include <cuda_runtime.h>

#define NMAX 100000
#define EMAX 3200000
#define HDIM 64

// Scratch (no allocations allowed)
__device__ __align__(128) int   g_cnt[NMAX];          // in-degree (no self loop)
__device__ __align__(128) int   g_off[NMAX];          // segment start
__device__ __align__(128) int   g_cur[NMAX];          // sort cursor
__device__ __align__(128) int   g_bsum[512];          // scan block sums
__device__ __align__(128) float g_dis[NMAX];          // rsqrt(deg)
__device__ __align__(128) int   g_srow[EMAX];         // src idx sorted by target
__device__ __align__(128) float g_xs1a[NMAX * 16];    // x * dis  (16-dim!)
__device__ __align__(128) float g_agg [NMAX * 16];    // aggregated 16-dim
__device__ __align__(128) float g_xs2 [NMAX * HDIM];  // xw2 * dis

// ---------------------------------------------------------------------------
// Phase 0: counting sort of edges by target (edge_index is int32)
// ---------------------------------------------------------------------------
__global__ void k_zero(int n) {
    int i = blockIdx.x * blockDim.x + threadIdx.x;
    if (i < n) g_cnt[i] = 0;
}

__global__ void k_count(const int* __restrict__ ei, int E) {
    int p = blockIdx.x * blockDim.x + threadIdx.x;
    int base = p * 2;
    if (base + 1 < E) {
        int2 c = *(const int2*)(ei + E + base);   // E even -> 8B aligned
        atomicAdd(&g_cnt[c.x], 1);
        atomicAdd(&g_cnt[c.y], 1);
    } else if (base < E) {
        atomicAdd(&g_cnt[__ldg(&ei[E + base])], 1);
    }
}

__global__ void k_scan1(int n) {
    __shared__ int s[256];
    int t = threadIdx.x;
    int i = blockIdx.x * 256 + t;
    int v = (i < n) ? g_cnt[i] : 0;
    s[t] = v;
    __syncthreads();
#pragma unroll
    for (int o = 1; o < 256; o <<= 1) {
        int u = (t >= o) ? s[t - o] : 0;
        __syncthreads();
        s[t] += u;
        __syncthreads();
    }
    if (i < n) g_off[i] = s[t] - v;
    if (t == 255) g_bsum[blockIdx.x] = s[255];
}

__global__ void k_scan2(int nb) {
    __shared__ int s[512];
    int t = threadIdx.x;
    int v = (t < nb) ? g_bsum[t] : 0;
    s[t] = v;
    __syncthreads();
#pragma unroll
    for (int o = 1; o < 512; o <<= 1) {
        int u = (t >= o) ? s[t - o] : 0;
        __syncthreads();
        s[t] += u;
        __syncthreads();
    }
    if (t < nb) g_bsum[t] = s[t] - v;
}

__global__ void k_scan3(int n) {
    int i = blockIdx.x * 256 + threadIdx.x;
    if (i < n) {
        int o = g_off[i] + g_bsum[blockIdx.x];
        g_off[i] = o;
        g_cur[i] = o;
        g_dis[i] = rsqrtf((float)(g_cnt[i] + 1));
    }
}

__global__ void k_sort(const int* __restrict__ ei, int E) {
    int p = blockIdx.x * blockDim.x + threadIdx.x;
    int base = p * 2;
    if (base + 1 < E) {
        int2 r = *(const int2*)(ei + base);
        int2 c = *(const int2*)(ei + E + base);
        int p0 = atomicAdd(&g_cur[c.x], 1);
        int p1 = atomicAdd(&g_cur[c.y], 1);
        g_srow[p0] = r.x;
        g_srow[p1] = r.y;
    } else if (base < E) {
        int r = __ldg(&ei[base]);
        int c = __ldg(&ei[E + base]);
        g_srow[atomicAdd(&g_cur[c], 1)] = r;
    }
}

// ---------------------------------------------------------------------------
// Pre-scale: xs1a[n] = x[n] * dis[n]   (16 floats/node, 4 threads/node)
// ---------------------------------------------------------------------------
__global__ void k_pre(const float* __restrict__ x, int n) {
    int gtid = blockIdx.x * blockDim.x + threadIdx.x;
    int node = gtid >> 2;
    if (node >= n) return;
    float d = g_dis[node];
    float4 v = __ldg(((const float4*)x) + gtid);
    float4 o = make_float4(v.x * d, v.y * d, v.z * d, v.w * d);
    ((float4*)g_xs1a)[gtid] = o;
}

// ---------------------------------------------------------------------------
// Gather 1 (16-dim): agg[c] = dis[c] * (xs1a[c] + sum xs1a[row])
// 4 threads/node, one float4 lane each. 2 edges/iteration for MLP>=2.
// ---------------------------------------------------------------------------
__global__ void __launch_bounds__(256) k_gather1(int n) {
    int gtid = blockIdx.x * blockDim.x + threadIdx.x;
    int node = gtid >> 2;
    int q = gtid & 3;
    if (node >= n) return;
    const float4* xs = (const float4*)g_xs1a;

    float d   = g_dis[node];
    int   s   = g_off[node];
    int   cnt = g_cnt[node];

    float4 a = xs[node * 4 + q];
    float ax = a.x, ay = a.y, az = a.z, aw = a.w;
    float bx = 0.0f, by = 0.0f, bz = 0.0f, bw = 0.0f;

    int e = s + cnt;
    int i = s;
    for (; i + 1 < e; i += 2) {
        int r0 = __ldg(&g_srow[i]);
        int r1 = __ldg(&g_srow[i + 1]);
        float4 v0 = __ldg(&xs[r0 * 4 + q]);
        float4 v1 = __ldg(&xs[r1 * 4 + q]);
        ax += v0.x; ay += v0.y; az += v0.z; aw += v0.w;
        bx += v1.x; by += v1.y; bz += v1.z; bw += v1.w;
    }
    if (i < e) {
        int r0 = __ldg(&g_srow[i]);
        float4 v0 = __ldg(&xs[r0 * 4 + q]);
        ax += v0.x; ay += v0.y; az += v0.z; aw += v0.w;
    }
    float4 o = make_float4((ax + bx) * d, (ay + by) * d,
                           (az + bz) * d, (aw + bw) * d);
    ((float4*)g_agg)[node * 4 + q] = o;
}

// ---------------------------------------------------------------------------
// Fused GEMMs: xs2 = relu(agg @ W1 + b1) @ W2 * dis
// 4 nodes / 256-thread block. W1 (4KB) + W2 (16KB) + b1 staged in shared.
// ---------------------------------------------------------------------------
__global__ void __launch_bounds__(256) k_gemm12(const float* __restrict__ W1,
                                                const float* __restrict__ b1,
                                                const float* __restrict__ W2,
                                                int n) {
    __shared__ float sW1[16 * 64];
    __shared__ float sW2[64 * 64];
    __shared__ float sb1[64];
    __shared__ float sa[4][16];
    __shared__ float sh[4][64];
    int t = threadIdx.x;
    for (int i = t; i < 16 * 64; i += 256) sW1[i] = W1[i];
    for (int i = t; i < 64 * 64; i += 256) sW2[i] = W2[i];
    if (t < 64) sb1[t] = b1[t];

    int node0 = blockIdx.x * 4;
    if (t < 64) {
        int nn = t >> 4, k = t & 15;
        int node = node0 + nn;
        sa[nn][k] = (node < n) ? g_agg[node * 16 + k] : 0.0f;
    }
    __syncthreads();

    int nn = t >> 6, f = t & 63;
    // h1 = relu(agg @ W1 + b1)
    {
        float acc = sb1[f];
#pragma unroll
        for (int k = 0; k < 16; k++) acc += sa[nn][k] * sW1[k * 64 + f];
        sh[nn][f] = fmaxf(acc, 0.0f);
    }
    __syncthreads();

    int node = node0 + nn;
    if (node < n) {
        float acc = 0.0f;
#pragma unroll
        for (int k = 0; k < 64; k++) acc += sh[nn][k] * sW2[k * 64 + f];
        g_xs2[(size_t)node * HDIM + f] = acc * g_dis[node];
    }
}

// ---------------------------------------------------------------------------
// Gather 2 (64-dim) + fused head:
//   h2 = dis[c]*(xs2[c] + sum xs2[row]) + b2
//   out[c] = sigmoid( relu(h2) . Wf + bf )
// 16 threads/node; 2 edges/iteration; width-16 shuffle reduction;
// h2 never materialized.
// ---------------------------------------------------------------------------
__global__ void __launch_bounds__(256) k_gather2(const float* __restrict__ b2,
                                                 const float* __restrict__ Wf,
                                                 const float* __restrict__ bf,
                                                 float* __restrict__ out, int n) {
    int gtid = blockIdx.x * blockDim.x + threadIdx.x;
    int node = gtid >> 4;
    int q = gtid & 15;
    bool valid = (node < n);
    if (node >= n) node = n - 1;            // clamp: keep all lanes for shuffles
    const float4* xs = (const float4*)g_xs2;

    float4 bb = __ldg(((const float4*)b2) + q);
    float4 wf = __ldg(((const float4*)Wf) + q);
    float  d   = g_dis[node];
    int    s   = g_off[node];
    int    cnt = g_cnt[node];

    float4 a = xs[(size_t)node * 16 + q];
    float ax = a.x, ay = a.y, az = a.z, aw = a.w;
    float cx = 0.0f, cy = 0.0f, cz = 0.0f, cw = 0.0f;

    int e = s + cnt;
    int i = s;
    for (; i + 1 < e; i += 2) {
        int r0 = __ldg(&g_srow[i]);
        int r1 = __ldg(&g_srow[i + 1]);
        float4 v0 = __ldg(&xs[(size_t)r0 * 16 + q]);
        float4 v1 = __ldg(&xs[(size_t)r1 * 16 + q]);
        ax += v0.x; ay += v0.y; az += v0.z; aw += v0.w;
        cx += v1.x; cy += v1.y; cz += v1.z; cw += v1.w;
    }
    if (i < e) {
        int r0 = __ldg(&g_srow[i]);
        float4 v0 = __ldg(&xs[(size_t)r0 * 16 + q]);
        ax += v0.x; ay += v0.y; az += v0.z; aw += v0.w;
    }
    ax += cx; ay += cy; az += cz; aw += cw;

    // h2 lane values + partial head dot
    float p = fmaxf(ax * d + bb.x, 0.0f) * wf.x
            + fmaxf(ay * d + bb.y, 0.0f) * wf.y
            + fmaxf(az * d + bb.z, 0.0f) * wf.z
            + fmaxf(aw * d + bb.w, 0.0f) * wf.w;
#pragma unroll
    for (int o = 8; o > 0; o >>= 1) p += __shfl_down_sync(0xffffffffu, p, o, 16);
    if (valid && q == 0) {
        float z = p + __ldg(&bf[0]);
        out[node] = 1.0f / (1.0f + expf(-z));
    }
}

// ---------------------------------------------------------------------------
extern "C" void kernel_launch(void* const* d_in, const int* in_sizes, int n_in,
                              void* d_out, int out_size) {
    const float* x  = (const float*)d_in[0];
    const int*   ei = (const int*)d_in[1];    // int32 (JAX x64 disabled)
    const float* W1 = (const float*)d_in[2];
    const float* b1 = (const float*)d_in[3];
    const float* W2 = (const float*)d_in[4];
    const float* b2 = (const float*)d_in[5];
    const float* Wf = (const float*)d_in[6];
    const float* bf = (const float*)d_in[7];
    float* out = (float*)d_out;

    int N = in_sizes[0] / 16;   // 100000
    int E = in_sizes[1] / 2;    // 3200000

    int nb  = (N + 255) / 256;              // 391 (<= 512 for scan2)
    int ebp = (E / 2 + 255) / 256;          // paired edge blocks
    int gb  = (N + 3) / 4;
    int g1b = (N * 4 + 255) / 256;
    int g2b = (N * 16 + 255) / 256;

    // sort phase
    k_zero  <<<nb, 256>>>(N);
    k_count <<<ebp, 256>>>(ei, E);
    k_scan1 <<<nb, 256>>>(N);
    k_scan2 <<<1, 512>>>(nb);
    k_scan3 <<<nb, 256>>>(N);
    k_sort  <<<ebp, 256>>>(ei, E);

    // layer 1: pre-scale -> 16-dim aggregate -> fused GEMMs
    k_pre     <<<g1b, 256>>>(x, N);
    k_gather1 <<<g1b, 256>>>(N);
    k_gemm12  <<<gb, 256>>>(W1, b1, W2, N);

    // layer 2 aggregate + head (fused)
    k_gather2 <<<g2b, 256>>>(b2, Wf, bf, out, N);
}